// round 1
// baseline (speedup 1.0000x reference)
#include <cuda_runtime.h>
#include <stdint.h>

// ProbabilisticPrediction: y = mu_sel + softplus(max(-15,s_sel)) * eps
// Key insight: only the categorical-selected component c = idx[b,q] is needed,
// so we compute idx first (Gumbel-argmax with JAX threefry RNG, key(1)) and
// evaluate the 3-layer MLP only at 1024 (b,q,idx) points instead of 512k.
//
// JAX RNG reproduced with jax_threefry_partitionable=True semantics (default
// in modern JAX): split is fold-like, random_bits[i] = o0^o1 of
// threefry2x32(key, (0, i)). Flip JAX_PARTITIONABLE to 0 for legacy layout.

#define JAX_PARTITIONABLE 1

#define B_   4
#define QL_  256
#define CL_  512
#define XD_  128
#define ED_  128
#define DIM_ 128
#define YD_  16

// ---------------------------------------------------------------- threefry2x32
__host__ __device__ inline void tf2x32(uint32_t k0, uint32_t k1,
                                       uint32_t c0, uint32_t c1,
                                       uint32_t& o0, uint32_t& o1) {
    uint32_t k2 = k0 ^ k1 ^ 0x1BD11BDAu;
    uint32_t x0 = c0 + k0, x1 = c1 + k1;
#define TFR(d) do { x0 += x1; x1 = (x1 << (d)) | (x1 >> (32 - (d))); x1 ^= x0; } while (0)
    TFR(13); TFR(15); TFR(26); TFR(6);   x0 += k1; x1 += k2 + 1u;
    TFR(17); TFR(29); TFR(16); TFR(24);  x0 += k2; x1 += k0 + 2u;
    TFR(13); TFR(15); TFR(26); TFR(6);   x0 += k0; x1 += k1 + 3u;
    TFR(17); TFR(29); TFR(16); TFR(24);  x0 += k1; x1 += k2 + 4u;
    TFR(13); TFR(15); TFR(26); TFR(6);   x0 += k2; x1 += k0 + 5u;
#undef TFR
    o0 = x0; o1 = x1;
}

// random_bits for flat element index j within an array of `total` elements.
__device__ inline uint32_t jax_random_bits(uint32_t k0, uint32_t k1,
                                           uint32_t j, uint32_t half_total) {
#if JAX_PARTITIONABLE
    (void)half_total;
    uint32_t o0, o1;
    tf2x32(k0, k1, 0u, j, o0, o1);   // 64-bit iota: hi=0, lo=j
    return o0 ^ o1;
#else
    // legacy: counts iota split into halves, pairs (j, j+half)
    uint32_t o0, o1;
    if (j < half_total) { tf2x32(k0, k1, j, j + half_total, o0, o1); return o0; }
    tf2x32(k0, k1, j - half_total, j, o0, o1); return o1;
#endif
}

__device__ inline float bits_to_unit(uint32_t b) {      // [0, 1)
    return __uint_as_float((b >> 9) | 0x3f800000u) - 1.0f;
}

// XLA ErfInv32 (Giles) -- matches jax.random.normal exactly.
__device__ inline float erfinv_xla(float x) {
    float w = -log1pf(-x * x);
    float p;
    if (w < 5.0f) {
        w -= 2.5f;
        p =            2.81022636e-08f;
        p = fmaf(p, w, 3.43273939e-07f);
        p = fmaf(p, w, -3.5233877e-06f);
        p = fmaf(p, w, -4.39150654e-06f);
        p = fmaf(p, w, 0.00021858087f);
        p = fmaf(p, w, -0.00125372503f);
        p = fmaf(p, w, -0.00417768164f);
        p = fmaf(p, w, 0.246640727f);
        p = fmaf(p, w, 1.50140941f);
    } else {
        w = sqrtf(w) - 3.0f;
        p =            -0.000200214257f;
        p = fmaf(p, w, 0.000100950558f);
        p = fmaf(p, w, 0.00134934322f);
        p = fmaf(p, w, -0.00367342844f);
        p = fmaf(p, w, 0.00573950773f);
        p = fmaf(p, w, -0.0076224613f);
        p = fmaf(p, w, 0.00943887047f);
        p = fmaf(p, w, 1.00167406f);
        p = fmaf(p, w, 2.83297682f);
    }
    return p * x;
}

// ---------------------------------------------------------------------- kernel
__global__ __launch_bounds__(128)
void pp_fused_kernel(const float* __restrict__ q,
                     const float* __restrict__ f_embed,
                     const float* __restrict__ att_logits,
                     const float* __restrict__ W1q,
                     const float* __restrict__ W1f,
                     const float* __restrict__ b1,
                     const float* __restrict__ W2,
                     const float* __restrict__ b2,
                     const float* __restrict__ Wout,
                     const float* __restrict__ bout,
                     float* __restrict__ out,
                     uint32_t kc0, uint32_t kc1,   // categorical key
                     uint32_t ke0, uint32_t ke1)   // eps key
{
    const int t  = threadIdx.x;          // 0..127
    const int bq = blockIdx.x;           // b*QL + ql
    const int b  = bq >> 8;

    __shared__ float sA[DIM_];
    __shared__ float sB[DIM_];
    __shared__ float sH[DIM_];
    __shared__ float sO[2 * YD_];
    __shared__ int   sI[DIM_];

    // ---------------- Phase 1: idx = argmax_c (gumbel + logits) -------------
    const uint32_t HALF_G = (uint32_t)(B_ * QL_ * CL_ / 2);
    const float TINY = 1.17549435e-38f;
    float best = -__int_as_float(0x7f800000);   // -inf
    int bi = 0;
    const float* lrow = att_logits + (size_t)bq * CL_;
#pragma unroll
    for (int k = 0; k < CL_ / 128; ++k) {
        int c = t + k * 128;
        uint32_t j = (uint32_t)bq * (uint32_t)CL_ + (uint32_t)c;
        float u = bits_to_unit(jax_random_bits(kc0, kc1, j, HALF_G));
        u = fmaxf(TINY, u * (1.0f - TINY) + TINY);
        float g = -logf(-logf(u));
        float v = g + lrow[c];
        if (v > best || (v == best && c < bi)) { best = v; bi = c; }
    }
    sA[t] = best; sI[t] = bi;
    __syncthreads();
    for (int off = 64; off; off >>= 1) {
        if (t < off) {
            float v2 = sA[t + off]; int i2 = sI[t + off];
            if (v2 > sA[t] || (v2 == sA[t] && i2 < sI[t])) { sA[t] = v2; sI[t] = i2; }
        }
        __syncthreads();
    }
    const int idx = sI[0];
    __syncthreads();

    // ---------------- Phase 2: fused MLP at the selected component ----------
    sA[t] = q[(size_t)bq * XD_ + t];                       // q row
    sB[t] = f_embed[((size_t)b * CL_ + idx) * ED_ + t];    // selected f row
    __syncthreads();

    float acc = b1[t];
#pragma unroll 8
    for (int d = 0; d < DIM_; ++d)
        acc = fmaf(sA[d], W1q[d * DIM_ + t], fmaf(sB[d], W1f[d * DIM_ + t], acc));
    sH[t] = fmaxf(acc, 0.0f);
    __syncthreads();

    float acc2 = b2[t];
#pragma unroll 8
    for (int d = 0; d < DIM_; ++d)
        acc2 = fmaf(sH[d], W2[d * DIM_ + t], acc2);
    sA[t] = fmaxf(acc2, 0.0f);                              // h2
    __syncthreads();

    if (t < 2 * YD_) {
        float o = bout[t];
#pragma unroll 8
        for (int d = 0; d < DIM_; ++d)
            o = fmaf(sA[d], Wout[d * (2 * YD_) + t], o);
        sO[t] = o;
    }
    __syncthreads();

    if (t < YD_) {
        const uint32_t HALF_E = (uint32_t)(B_ * QL_ * YD_ / 2);
        uint32_t m = (uint32_t)bq * (uint32_t)YD_ + (uint32_t)t;
        float u = bits_to_unit(jax_random_bits(ke0, ke1, m, HALF_E));
        const float lo = -0.99999994f;
        float x = fmaxf(lo, u * (1.0f - lo) + lo);
        float eps = 1.41421356237f * erfinv_xla(x);
        float s = fmaxf(-15.0f, sO[YD_ + t]);
        float sigma = fmaxf(s, 0.0f) + log1pf(expf(-fabsf(s)));   // softplus
        out[(size_t)bq * YD_ + t] = fmaf(sigma, eps, sO[t]);
    }
}

// ---------------------------------------------------------------------- launch
extern "C" void kernel_launch(void* const* d_in, const int* in_sizes, int n_in,
                              void* d_out, int out_size) {
    const float* q     = (const float*)d_in[0];
    const float* f_emb = (const float*)d_in[1];
    const float* alog  = (const float*)d_in[2];
    const float* W1q   = (const float*)d_in[3];
    const float* W1f   = (const float*)d_in[4];
    const float* b1    = (const float*)d_in[5];
    const float* W2    = (const float*)d_in[6];
    const float* b2    = (const float*)d_in[7];
    const float* Wout  = (const float*)d_in[8];
    const float* bout  = (const float*)d_in[9];
    float* out = (float*)d_out;

    // split(jax.random.key(1), 2): key words = (0, 1)
    uint32_t kc0, kc1, ke0, ke1;
#if JAX_PARTITIONABLE
    // fold-like: subkey_i = threefry(key, (0, i))
    tf2x32(0u, 1u, 0u, 0u, kc0, kc1);
    tf2x32(0u, 1u, 0u, 1u, ke0, ke1);
#else
    // legacy: counts [0,1,2,3] -> lanes (0,2),(1,3); keys from concat+reshape
    uint32_t a0, a1, b0, b1_;
    tf2x32(0u, 1u, 0u, 2u, a0, a1);
    tf2x32(0u, 1u, 1u, 3u, b0, b1_);
    kc0 = a0; kc1 = b0; ke0 = a1; ke1 = b1_;
#endif

    pp_fused_kernel<<<B_ * QL_, 128>>>(q, f_emb, alog, W1q, W1f, b1, W2, b2,
                                       Wout, bout, out, kc0, kc1, ke0, ke1);
}